// round 2
// baseline (speedup 1.0000x reference)
#include <cuda_runtime.h>
#include <math.h>

#define CDIV(a,b) (((a)+(b)-1)/(b))

static constexpr int B  = 32;
static constexpr int KN = 16;     // neighborhood size
static constexpr int N0 = 2048, N1 = 512, N2 = 128;

// ---------------- scratch (device globals; no allocation allowed) ----------------
static constexpr size_t OFF_F0  = 0;                                  // B*8*N0
static constexpr size_t OFF_G1  = OFF_F0  + (size_t)B*8*N0;           // B*N0*32
static constexpr size_t OFF_H1  = OFF_G1  + (size_t)B*N0*32;          // B*N0*32
static constexpr size_t OFF_M1  = OFF_H1  + (size_t)B*N0*32;
static constexpr size_t OFF_MN1 = OFF_M1  + (size_t)B*N0*32;
static constexpr size_t OFF_F1  = OFF_MN1 + (size_t)B*N0*32;          // B*32*N0
static constexpr size_t OFF_CQ1 = OFF_F1  + (size_t)B*32*N0;          // B*3*N1
static constexpr size_t OFF_FQ1 = OFF_CQ1 + (size_t)B*3*N1;           // B*32*N1
static constexpr size_t OFF_G2  = OFF_FQ1 + (size_t)B*32*N1;          // B*N0*64
static constexpr size_t OFF_H2  = OFF_G2  + (size_t)B*N0*64;          // B*N1*64
static constexpr size_t OFF_M2  = OFF_H2  + (size_t)B*N1*64;
static constexpr size_t OFF_MN2 = OFF_M2  + (size_t)B*N1*64;
static constexpr size_t OFF_F2  = OFF_MN2 + (size_t)B*N1*64;          // B*64*N1
static constexpr size_t OFF_G3  = OFF_F2  + (size_t)B*64*N1;          // B*N1*64
static constexpr size_t OFF_H3  = OFF_G3  + (size_t)B*N1*64;
static constexpr size_t OFF_M3  = OFF_H3  + (size_t)B*N1*64;
static constexpr size_t OFF_MN3 = OFF_M3  + (size_t)B*N1*64;
static constexpr size_t OFF_F3  = OFF_MN3 + (size_t)B*N1*64;          // B*64*N1
static constexpr size_t OFF_FQ3 = OFF_F3  + (size_t)B*64*N1;          // B*64*N2
static constexpr size_t OFF_G4  = OFF_FQ3 + (size_t)B*64*N2;          // B*N1*128
static constexpr size_t OFF_H4  = OFF_G4  + (size_t)B*N1*128;         // B*N2*128
static constexpr size_t OFF_M4  = OFF_H4  + (size_t)B*N2*128;
static constexpr size_t OFF_MN4 = OFF_M4  + (size_t)B*N2*128;
static constexpr size_t FBUF_TOTAL = OFF_MN4 + (size_t)B*N2*128;

__device__ float d_fbuf[FBUF_TOTAL];

static constexpr size_t IOFF_IDX1 = 0;                                // B*N0*KN
static constexpr size_t IOFF_FPS1 = IOFF_IDX1 + (size_t)B*N0*KN;      // B*N1
static constexpr size_t IOFF_IDX2 = IOFF_FPS1 + (size_t)B*N1;         // B*N1*KN
static constexpr size_t IOFF_IDX3 = IOFF_IDX2 + (size_t)B*N1*KN;      // B*N1*KN
static constexpr size_t IOFF_FPS2 = IOFF_IDX3 + (size_t)B*N1*KN;      // B*N2
static constexpr size_t IOFF_IDX4 = IOFF_FPS2 + (size_t)B*N2;         // B*N2*KN
static constexpr size_t IBUF_TOTAL = IOFF_IDX4 + (size_t)B*N2*KN;

__device__ int d_ibuf[IBUF_TOTAL];
__device__ double d_statsbuf[4 * B * 4 * 2];   // [layer][b][group][{sum,sumsq}]

// ---------------- kernels ----------------

__global__ void k_zero_stats(double* p, int n) {
    int t = blockIdx.x * blockDim.x + threadIdx.x;
    if (t < n) p[t] = 0.0;
}

// f0[b,o,n] = sum_c w[o,c]*x[b,c,n] + bias[o]
__global__ void k_lin_in(const float* __restrict__ x, const float* __restrict__ w,
                         const float* __restrict__ bias, float* __restrict__ f0) {
    int t = blockIdx.x * blockDim.x + threadIdx.x;
    if (t >= B * N0) return;
    int b = t / N0, n = t % N0;
    float x0 = x[(b*3+0)*N0 + n];
    float x1 = x[(b*3+1)*N0 + n];
    float x2 = x[(b*3+2)*N0 + n];
#pragma unroll
    for (int o = 0; o < 8; o++) {
        float v = w[o*3+0]*x0 + w[o*3+1]*x1 + w[o*3+2]*x2 + bias[o];
        f0[(b*8+o)*N0 + n] = v;
    }
}

// KNN: for each query, top-16 smallest (sqq + sqk - 2*inner) among NK keys.
template<int NK>
__global__ void k_knn(const float* __restrict__ cq, const float* __restrict__ ck,
                      int Nq, int* __restrict__ idx_out) {
    __shared__ float4 skey[NK];
    int b = blockIdx.y;
    const float* ckb = ck + (size_t)b*3*NK;
    for (int j = threadIdx.x; j < NK; j += blockDim.x) {
        float kx = ckb[j], ky = ckb[NK + j], kz = ckb[2*NK + j];
        skey[j] = make_float4(kx, ky, kz, kx*kx + ky*ky + kz*kz);
    }
    __syncthreads();
    int q = blockIdx.x * blockDim.x + threadIdx.x;
    if (q >= Nq) return;
    const float* cqb = cq + (size_t)b*3*Nq;
    float qx = cqb[q], qy = cqb[Nq + q], qz = cqb[2*Nq + q];
    float sqq = qx*qx + qy*qy + qz*qz;

    float bd[KN]; int bi[KN];
#pragma unroll
    for (int i = 0; i < KN; i++) { bd[i] = 3.4e38f; bi[i] = 0; }

    for (int j = 0; j < NK; j++) {
        float4 kk = skey[j];
        float inner = qx*kk.x + qy*kk.y + qz*kk.z;
        float d = sqq + kk.w - 2.0f*inner;
        if (d < bd[KN-1]) {                 // strict <  => lower index wins ties
            bd[KN-1] = d; bi[KN-1] = j;
#pragma unroll
            for (int i = KN-1; i > 0; --i) {
                if (bd[i] < bd[i-1]) {
                    float tv = bd[i]; bd[i] = bd[i-1]; bd[i-1] = tv;
                    int   ti = bi[i]; bi[i] = bi[i-1]; bi[i-1] = ti;
                }
            }
        }
    }
    int* ob = idx_out + ((size_t)b*Nq + q) * KN;
#pragma unroll
    for (int i = 0; i < KN; i++) ob[i] = bi[i];
}

// Furthest point sampling. One block per batch. Matches jax scan semantics:
// out[s] = last; dist = min(dist, d(centroid=last)); last = argmax(dist) (first max).
template<int N, int S, int BLK>
__global__ void k_fps(const float* __restrict__ coor, int* __restrict__ out) {
    constexpr int PPT = N / BLK;
    constexpr int NW  = BLK / 32;
    __shared__ float sx[N], sy[N], sz[N];
    __shared__ float swv[32];
    __shared__ int   swi[32];
    __shared__ int   sres;
    int b = blockIdx.x, t = threadIdx.x;
    int lane = t & 31, w = t >> 5;
    const float* cb = coor + (size_t)b*3*N;
    for (int i = t; i < N; i += BLK) { sx[i] = cb[i]; sy[i] = cb[N+i]; sz[i] = cb[2*N+i]; }
    __syncthreads();

    float dist[PPT];
#pragma unroll
    for (int p = 0; p < PPT; p++) dist[p] = 1e10f;
    int last = 0;

    for (int s = 0; s < S; s++) {
        if (t == 0) out[(size_t)b*S + s] = last;
        float cx = sx[last], cy = sy[last], cz = sz[last];
        float bv = -1.0f; int bidx = 0x7fffffff;
#pragma unroll
        for (int p = 0; p < PPT; p++) {
            int i = t + p * BLK;
            float dx = sx[i]-cx, dy = sy[i]-cy, dz = sz[i]-cz;
            float d = dx*dx + dy*dy + dz*dz;
            float nd = fminf(dist[p], d);
            dist[p] = nd;
            if (nd > bv) { bv = nd; bidx = i; }   // ascending i => first-max kept
        }
#pragma unroll
        for (int off = 16; off > 0; off >>= 1) {
            float ov = __shfl_down_sync(0xffffffffu, bv, off);
            int   oi = __shfl_down_sync(0xffffffffu, bidx, off);
            if (ov > bv || (ov == bv && oi < bidx)) { bv = ov; bidx = oi; }
        }
        if (lane == 0) { swv[w] = bv; swi[w] = bidx; }
        __syncthreads();
        if (w == 0) {
            float v = (lane < NW) ? swv[lane] : -1.0f;
            int  ii = (lane < NW) ? swi[lane] : 0x7fffffff;
#pragma unroll
            for (int off = 16; off > 0; off >>= 1) {
                float ov = __shfl_down_sync(0xffffffffu, v, off);
                int   oi = __shfl_down_sync(0xffffffffu, ii, off);
                if (ov > v || (ov == v && oi < ii)) { v = ov; ii = oi; }
            }
            if (lane == 0) sres = ii;
        }
        __syncthreads();
        last = sres;
        __syncthreads();
    }
}

// gather: dst[b,c,s] = src[b,c,idx[b,s]]
__global__ void k_gather(const float* __restrict__ src, const int* __restrict__ idx,
                         int C, int Nin, int S, float* __restrict__ dst) {
    int b = blockIdx.y;
    int t = blockIdx.x * blockDim.x + threadIdx.x;
    if (t >= C * S) return;
    int c = t / S, s = t % S;
    dst[((size_t)b*C + c)*S + s] = src[((size_t)b*C + c)*Nin + idx[(size_t)b*S + s]];
}

// GEMM: g[b,j,o] = sum_c wsel[o,c] * f[b,c,j]
// DIFF=false: wsel = w[o, c]          (key-part, first C columns of (Cout,2C))
// DIFF=true : wsel = w[o, C+c] - w[o, c]
template<int C, int Cout, bool DIFF>
__global__ void k_gemm(const float* __restrict__ f, const float* __restrict__ w,
                       int Nk, float* __restrict__ g) {
    constexpr int OC = Cout / 4;
    __shared__ float ws[C * Cout];    // transposed: ws[c*Cout + o]
    int b = blockIdx.y;
    for (int i = threadIdx.x; i < C * Cout; i += blockDim.x) {
        int c = i / Cout, o = i % Cout;
        float v = w[o*2*C + c];
        if (DIFF) v = w[o*2*C + C + c] - v;
        ws[c*Cout + o] = v;
    }
    __syncthreads();
    int t = blockIdx.x * blockDim.x + threadIdx.x;
    int j = t / OC, oc = t % OC;
    if (j >= Nk) return;
    const float* fb = f + (size_t)b*C*Nk;
    float a0 = 0.f, a1 = 0.f, a2 = 0.f, a3 = 0.f;
#pragma unroll
    for (int c = 0; c < C; c++) {
        float fv = fb[(size_t)c*Nk + j];
        float4 wv = *(const float4*)&ws[c*Cout + oc*4];
        a0 += fv * wv.x; a1 += fv * wv.y; a2 += fv * wv.z; a3 += fv * wv.w;
    }
    *(float4*)&g[((size_t)b*Nk + j)*Cout + oc*4] = make_float4(a0, a1, a2, a3);
}

// fused: y[o,n,k] = g[j(n,k),o] + h[n,o]; track max_k/min_k per (n,o),
// and accumulate group sum/sumsq (GroupNorm stats over (C/4, Nq, K) per batch/group).
template<int Cout>
__global__ void k_stats_max(const float* __restrict__ g, const float* __restrict__ h,
                            const int* __restrict__ idx, int Nq, int Nk,
                            float* __restrict__ mx, float* __restrict__ mn,
                            double* __restrict__ stats) {
    constexpr int OC = Cout / 4;
    __shared__ float ssum[4], ssq[4];
    int b = blockIdx.y;
    if (threadIdx.x < 4) { ssum[threadIdx.x] = 0.f; ssq[threadIdx.x] = 0.f; }
    __syncthreads();
    int t = blockIdx.x * blockDim.x + threadIdx.x;
    int n = t / OC, oc = t % OC;
    float s = 0.f, ss = 0.f;
    int grp = 0;
    if (n < Nq) {
        grp = (oc * 16) / Cout;   // 4 channels per thread, Cout/4 channels per group
        const int* ib = idx + ((size_t)b*Nq + n) * KN;
        float4 hv = *(const float4*)&h[((size_t)b*Nq + n)*Cout + oc*4];
        float4 m4 = make_float4(-3.4e38f, -3.4e38f, -3.4e38f, -3.4e38f);
        float4 n4 = make_float4( 3.4e38f,  3.4e38f,  3.4e38f,  3.4e38f);
#pragma unroll
        for (int k = 0; k < KN; k++) {
            int j = ib[k];
            float4 gv = *(const float4*)&g[((size_t)b*Nk + j)*Cout + oc*4];
            float y0 = gv.x + hv.x, y1 = gv.y + hv.y, y2 = gv.z + hv.z, y3 = gv.w + hv.w;
            m4.x = fmaxf(m4.x, y0); m4.y = fmaxf(m4.y, y1);
            m4.z = fmaxf(m4.z, y2); m4.w = fmaxf(m4.w, y3);
            n4.x = fminf(n4.x, y0); n4.y = fminf(n4.y, y1);
            n4.z = fminf(n4.z, y2); n4.w = fminf(n4.w, y3);
            s  += (y0 + y1) + (y2 + y3);
            ss += (y0*y0 + y1*y1) + (y2*y2 + y3*y3);
        }
        *(float4*)&mx[((size_t)b*Nq + n)*Cout + oc*4] = m4;
        *(float4*)&mn[((size_t)b*Nq + n)*Cout + oc*4] = n4;
    }
    atomicAdd(&ssum[grp], s);
    atomicAdd(&ssq[grp], ss);
    __syncthreads();
    if (threadIdx.x < 4) {
        atomicAdd(&stats[((size_t)b*4 + threadIdx.x)*2 + 0], (double)ssum[threadIdx.x]);
        atomicAdd(&stats[((size_t)b*4 + threadIdx.x)*2 + 1], (double)ssq[threadIdx.x]);
    }
}

// finalize: f_out[b,o,n] = lrelu((sel - mean)*rstd*gamma[o] + beta[o]),
// sel = max if gamma>=0 else min (monotone-commuted through norm+lrelu).
template<int Cout>
__global__ void k_finalize(const float* __restrict__ mx, const float* __restrict__ mn,
                           const double* __restrict__ stats,
                           const float* __restrict__ gamma, const float* __restrict__ beta,
                           int Nq, float* __restrict__ fout) {
    int b = blockIdx.y;
    int t = blockIdx.x * blockDim.x + threadIdx.x;
    if (t >= Cout * Nq) return;
    int o = t / Nq, n = t % Nq;
    int grp = o / (Cout / 4);
    double cnt = (double)(Cout / 4) * (double)Nq * (double)KN;
    double su = stats[((size_t)b*4 + grp)*2 + 0];
    double sq = stats[((size_t)b*4 + grp)*2 + 1];
    double m  = su / cnt;
    double vr = sq / cnt - m * m;
    float mean = (float)m;
    float rstd = rsqrtf((float)vr + 1e-5f);
    float ga = gamma[o], be = beta[o];
    float sel = (ga >= 0.f) ? mx[((size_t)b*Nq + n)*Cout + o]
                            : mn[((size_t)b*Nq + n)*Cout + o];
    float v = (sel - mean) * rstd * ga + be;
    fout[((size_t)b*Cout + o)*Nq + n] = (v >= 0.f) ? v : 0.2f * v;
}

// ---------------- launch ----------------
extern "C" void kernel_launch(void* const* d_in, const int* in_sizes, int n_in,
                              void* d_out, int out_size) {
    const float* x    = (const float*)d_in[0];
    const float* w_in = (const float*)d_in[1];
    const float* b_in = (const float*)d_in[2];
    const float* w1 = (const float*)d_in[3];
    const float* g1p = (const float*)d_in[4];
    const float* b1p = (const float*)d_in[5];
    const float* w2 = (const float*)d_in[6];
    const float* g2p = (const float*)d_in[7];
    const float* b2p = (const float*)d_in[8];
    const float* w3 = (const float*)d_in[9];
    const float* g3p = (const float*)d_in[10];
    const float* b3p = (const float*)d_in[11];
    const float* w4 = (const float*)d_in[12];
    const float* g4p = (const float*)d_in[13];
    const float* b4p = (const float*)d_in[14];

    float*  fb;  cudaGetSymbolAddress((void**)&fb,  d_fbuf);
    int*    ib;  cudaGetSymbolAddress((void**)&ib,  d_ibuf);
    double* st;  cudaGetSymbolAddress((void**)&st,  d_statsbuf);
    float*  out = (float*)d_out;

    float* f0  = fb + OFF_F0;
    float* g1  = fb + OFF_G1;  float* h1 = fb + OFF_H1;
    float* m1  = fb + OFF_M1;  float* mn1 = fb + OFF_MN1; float* f1 = fb + OFF_F1;
    float* cq1 = fb + OFF_CQ1; float* fq1 = fb + OFF_FQ1;
    float* g2  = fb + OFF_G2;  float* h2 = fb + OFF_H2;
    float* m2  = fb + OFF_M2;  float* mn2 = fb + OFF_MN2; float* f2 = fb + OFF_F2;
    float* g3  = fb + OFF_G3;  float* h3 = fb + OFF_H3;
    float* m3  = fb + OFF_M3;  float* mn3 = fb + OFF_MN3; float* f3 = fb + OFF_F3;
    float* fq3 = fb + OFF_FQ3;
    float* g4  = fb + OFF_G4;  float* h4 = fb + OFF_H4;
    float* m4  = fb + OFF_M4;  float* mn4 = fb + OFF_MN4;

    int* idx1 = ib + IOFF_IDX1; int* fps1 = ib + IOFF_FPS1;
    int* idx2 = ib + IOFF_IDX2; int* idx3 = ib + IOFF_IDX3;
    int* fps2 = ib + IOFF_FPS2; int* idx4 = ib + IOFF_IDX4;

    double* st1 = st + 0 * B * 8;
    double* st2 = st + 1 * B * 8;
    double* st3 = st + 2 * B * 8;
    double* st4 = st + 3 * B * 8;

    float* out_coor = out;                 // (B,3,128)
    float* out_f    = out + B * 3 * N2;    // (B,128,128)

    k_zero_stats<<<CDIV(4*B*8, 256), 256>>>(st, 4*B*8);
    k_lin_in<<<CDIV(B*N0, 256), 256>>>(x, w_in, b_in, f0);

    // stage 1 on full cloud
    k_knn<N0><<<dim3(CDIV(N0,256), B), 256>>>(x, x, N0, idx1);
    k_fps<N0, N1, 1024><<<B, 1024>>>(x, fps1);

    k_gemm<8, 32, false><<<dim3(CDIV(N0*8, 128), B), 128>>>(f0, w1, N0, g1);
    k_gemm<8, 32, true ><<<dim3(CDIV(N0*8, 128), B), 128>>>(f0, w1, N0, h1);
    k_stats_max<32><<<dim3(CDIV(N0*8, 128), B), 128>>>(g1, h1, idx1, N0, N0, m1, mn1, st1);
    k_finalize<32><<<dim3(CDIV(32*N0, 256), B), 256>>>(m1, mn1, st1, g1p, b1p, N0, f1);

    // sample 512
    k_gather<<<dim3(CDIV(3*N1, 256), B), 256>>>(x,  fps1, 3,  N0, N1, cq1);
    k_gather<<<dim3(CDIV(32*N1, 256), B), 256>>>(f1, fps1, 32, N0, N1, fq1);
    k_fps<N1, N2, 512><<<B, 512>>>(cq1, fps2);

    // stage 2: queries cq1 (512), keys x (2048)
    k_knn<N0><<<dim3(CDIV(N1,256), B), 256>>>(cq1, x, N1, idx2);
    k_gemm<32, 64, false><<<dim3(CDIV(N0*16, 128), B), 128>>>(f1,  w2, N0, g2);
    k_gemm<32, 64, true ><<<dim3(CDIV(N1*16, 128), B), 128>>>(fq1, w2, N1, h2);
    k_stats_max<64><<<dim3(CDIV(N1*16, 128), B), 128>>>(g2, h2, idx2, N1, N0, m2, mn2, st2);
    k_finalize<64><<<dim3(CDIV(64*N1, 256), B), 256>>>(m2, mn2, st2, g2p, b2p, N1, f2);

    // stage 3: queries = keys = cq1 (512)
    k_knn<N1><<<dim3(CDIV(N1,256), B), 256>>>(cq1, cq1, N1, idx3);
    k_gemm<64, 64, false><<<dim3(CDIV(N1*16, 128), B), 128>>>(f2, w3, N1, g3);
    k_gemm<64, 64, true ><<<dim3(CDIV(N1*16, 128), B), 128>>>(f2, w3, N1, h3);
    k_stats_max<64><<<dim3(CDIV(N1*16, 128), B), 128>>>(g3, h3, idx3, N1, N1, m3, mn3, st3);
    k_finalize<64><<<dim3(CDIV(64*N1, 256), B), 256>>>(m3, mn3, st3, g3p, b3p, N1, f3);

    // sample 128
    k_gather<<<dim3(CDIV(3*N2, 256), B), 256>>>(cq1, fps2, 3,  N1, N2, out_coor);
    k_gather<<<dim3(CDIV(64*N2, 256), B), 256>>>(f3,  fps2, 64, N1, N2, fq3);

    // stage 4: queries out_coor (128), keys cq1 (512)
    k_knn<N1><<<dim3(CDIV(N2,256), B), 256>>>(out_coor, cq1, N2, idx4);
    k_gemm<64, 128, false><<<dim3(CDIV(N1*32, 128), B), 128>>>(f3,  w4, N1, g4);
    k_gemm<64, 128, true ><<<dim3(CDIV(N2*32, 128), B), 128>>>(fq3, w4, N2, h4);
    k_stats_max<128><<<dim3(CDIV(N2*32, 128), B), 128>>>(g4, h4, idx4, N2, N1, m4, mn4, st4);
    k_finalize<128><<<dim3(CDIV(128*N2, 256), B), 256>>>(m4, mn4, st4, g4p, b4p, N2, out_f);
}